// round 16
// baseline (speedup 1.0000x reference)
#include <cuda_runtime.h>

// DWT Haar L1 loss — single fused persistent kernel (grid 512 x 256, uniform
// 24 groups/thread, batch-3 streaming loads), base address linear in k
// (one pointer increment per iteration, no per-iter shift/mask),
// double-atomic epilogue with last-ticket finalize.
//
// loss = sum_over_2x2_blocks( max(|a+b|,|c+d|) + max(|a-b|,|c-d|) ) / 6291456
// where a,b,c,d are the (pred-target) diffs of the 2x2 block.
// (Haar is linear; |u+v|+|u-v| = 2*max(|u|,|v|) cancels the 0.5 factor.)
//
// Index map: i = img*2^15 + r*2^7 + g, base = img*262144 + 2r*512 + 4g.
// STRIDE = 131072 groups = exactly 4 images, so stepping k -> k+1 adds
// 4*262144 = 1048576 elements to base with (r,g) unchanged.

#define NBLOCKS     512
#define NTHREADS    256
#define ITERS       24                        // 512*256*24 = 3145728 groups ✓
#define STEP_ELEMS  1048576u                  // 4 images per STRIDE step
#define INV_COUNT   (1.0 / 6291456.0)

__device__ double   g_sum   = 0.0;
__device__ unsigned g_count = 0;

__device__ __forceinline__ float block_term(
    float4 p0, float4 p1, float4 t0, float4 t1)
{
    float a0 = p0.x - t0.x, b0 = p0.y - t0.y;
    float c0 = p1.x - t1.x, d0 = p1.y - t1.y;
    float a1 = p0.z - t0.z, b1 = p0.w - t0.w;
    float c1 = p1.z - t1.z, d1 = p1.w - t1.w;

    return fmaxf(fabsf(a0 + b0), fabsf(c0 + d0))
         + fmaxf(fabsf(a0 - b0), fabsf(c0 - d0))
         + fmaxf(fabsf(a1 + b1), fabsf(c1 + d1))
         + fmaxf(fabsf(a1 - b1), fabsf(c1 - d1));
}

__global__ __launch_bounds__(NTHREADS, 4) void dwt_fused_kernel(
    const float* __restrict__ pred, const float* __restrict__ tgt,
    float* __restrict__ out)
{
    const unsigned i0 = blockIdx.x * NTHREADS + threadIdx.x;  // < 131072
    // base for k=0; thereafter base advances by STEP_ELEMS per k
    const unsigned base0 = ((i0 >> 7) << 10) | ((i0 & 127u) << 2);

    const float* pp = pred + base0;
    const float* tt = tgt  + base0;

    float acc = 0.0f;
    #pragma unroll 1
    for (int k = 0; k < ITERS; k += 3) {
        // 12 independent 128-bit streaming loads, front-batched for MLP;
        // all offsets are compile-time constants from (pp, tt)
        float4 pa0 = __ldcs(reinterpret_cast<const float4*>(pp));
        float4 pa1 = __ldcs(reinterpret_cast<const float4*>(pp + 512));
        float4 ta0 = __ldcs(reinterpret_cast<const float4*>(tt));
        float4 ta1 = __ldcs(reinterpret_cast<const float4*>(tt + 512));
        float4 pb0 = __ldcs(reinterpret_cast<const float4*>(pp + STEP_ELEMS));
        float4 pb1 = __ldcs(reinterpret_cast<const float4*>(pp + STEP_ELEMS + 512));
        float4 tb0 = __ldcs(reinterpret_cast<const float4*>(tt + STEP_ELEMS));
        float4 tb1 = __ldcs(reinterpret_cast<const float4*>(tt + STEP_ELEMS + 512));
        float4 pc0 = __ldcs(reinterpret_cast<const float4*>(pp + 2 * STEP_ELEMS));
        float4 pc1 = __ldcs(reinterpret_cast<const float4*>(pp + 2 * STEP_ELEMS + 512));
        float4 tc0 = __ldcs(reinterpret_cast<const float4*>(tt + 2 * STEP_ELEMS));
        float4 tc1 = __ldcs(reinterpret_cast<const float4*>(tt + 2 * STEP_ELEMS + 512));

        acc += block_term(pa0, pa1, ta0, ta1);
        acc += block_term(pb0, pb1, tb0, tb1);
        acc += block_term(pc0, pc1, tc0, tc1);

        pp += 3 * STEP_ELEMS;
        tt += 3 * STEP_ELEMS;
    }

    // ---- intra-block reduction ----
    #pragma unroll
    for (int off = 16; off > 0; off >>= 1)
        acc += __shfl_down_sync(0xFFFFFFFFu, acc, off);

    __shared__ float warp_sums[NTHREADS / 32];
    int lane = threadIdx.x & 31;
    int wid  = threadIdx.x >> 5;
    if (lane == 0) warp_sums[wid] = acc;
    __syncthreads();

    if (wid == 0) {
        float v = (lane < NTHREADS / 32) ? warp_sums[lane] : 0.0f;
        #pragma unroll
        for (int off = 4; off > 0; off >>= 1)
            v += __shfl_down_sync(0xFFFFFFFFu, v, off);
        if (lane == 0) {
            atomicAdd(&g_sum, (double)v);     // accumulate in double
            __threadfence();                  // publish before ticket
            unsigned t = atomicAdd(&g_count, 1u);
            if (t == NBLOCKS - 1) {
                // last block: all g_sum adds are visible (each preceded its ticket)
                out[0] = (float)(g_sum * INV_COUNT);
                g_sum   = 0.0;                // reset for next graph replay
                g_count = 0;
                __threadfence();
            }
        }
    }
}

extern "C" void kernel_launch(void* const* d_in, const int* in_sizes, int n_in,
                              void* d_out, int out_size) {
    const float* pred = (const float*)d_in[0];
    const float* tgt  = (const float*)d_in[1];
    float* out = (float*)d_out;

    dwt_fused_kernel<<<NBLOCKS, NTHREADS>>>(pred, tgt, out);
}